// round 6
// baseline (speedup 1.0000x reference)
#include <cuda_runtime.h>

// ---- problem constants ----
#define SB      1024
#define N1      8192
#define N2      16384
#define NTERMS  (N1 + N2)            // 24576
#define NC      5                    // chunks
#define CHUNK   5120                 // terms per chunk (last = 4096)
#define NSS     256
#define NT      256
#define ROWS    4
#define SPT     (SB / NT)            // 4 species per thread
#define NCTR    (SB * NC)            // 5120 sublists (species x chunk)
#define NROLES  (2 * N1 + 3 * N2)    // 65536
#define LIST_CAP (NROLES + NCTR + 8) // pad-to-2: <=1 waste per sublist

// ---- persistent scratch (rebuilt every launch; structure is input-constant) ----
__device__ int g_cnt[NCTR];
__device__ int g_cur[NCTR];
__device__ int g_off[NCTR + 1];
__device__ __align__(16) unsigned short g_list[LIST_CAP];

// dynamic smem: terms float4[CHUNK+1] | y4 float4[SB]
#define SMEM_BYTES (((CHUNK + 1) + SB) * 16)

__inline__ __device__ float warp_red(float v) {
    #pragma unroll
    for (int o = 16; o > 0; o >>= 1) v += __shfl_xor_sync(0xFFFFFFFFu, v, o);
    return v;
}

// ---------- build kernels ----------
__global__ void k_zero() {
    int i = blockIdx.x * blockDim.x + threadIdx.x;
    if (i < NCTR) g_cnt[i] = 0;
}

__device__ __forceinline__ void decode_role(
    int id, const int* p1, const int* r11, const int* p2,
    const int* r12, const int* r22, int& term, int& s, int& loss)
{
    if (id < N1)                 { term = id;                  s = __ldg(p1  + id);          loss = 0; }
    else if (id < 2 * N1)        { term = id - N1;             s = __ldg(r11 + id - N1);     loss = 1; }
    else if (id < 2 * N1 + N2)   { int j = id - 2 * N1;        term = N1 + j; s = __ldg(p2  + j); loss = 0; }
    else if (id < 2 * N1 + 2*N2) { int j = id - 2 * N1 - N2;   term = N1 + j; s = __ldg(r12 + j); loss = 1; }
    else                         { int j = id - 2 * N1 - 2*N2; term = N1 + j; s = __ldg(r22 + j); loss = 1; }
}

__global__ void k_count(const int* __restrict__ p1, const int* __restrict__ r11,
                        const int* __restrict__ p2, const int* __restrict__ r12,
                        const int* __restrict__ r22) {
    int id = blockIdx.x * blockDim.x + threadIdx.x;
    if (id >= NROLES) return;
    int term, s, loss;
    decode_role(id, p1, r11, p2, r12, r22, term, s, loss);
    int c = term / CHUNK;
    atomicAdd(&g_cnt[s * NC + c], 1);
}

__global__ void k_scan() {   // 1 CTA, 1024 threads, NC counters each
    __shared__ int sh[1024];
    int t = threadIdx.x;
    int pc[NC]; int tsum = 0;
    #pragma unroll
    for (int u = 0; u < NC; u++) {
        pc[u] = (g_cnt[t * NC + u] + 1) & ~1;   // pad to 2
        tsum += pc[u];
    }
    sh[t] = tsum;
    __syncthreads();
    for (int o = 1; o < 1024; o <<= 1) {
        int x = (t >= o) ? sh[t - o] : 0;
        __syncthreads();
        sh[t] += x;
        __syncthreads();
    }
    int excl = sh[t] - tsum;
    #pragma unroll
    for (int u = 0; u < NC; u++) {
        g_off[t * NC + u] = excl;
        g_cur[t * NC + u] = excl;
        excl += pc[u];
    }
    if (t == 1023) g_off[NCTR] = sh[1023];
}

__global__ void k_fill(const int* __restrict__ p1, const int* __restrict__ r11,
                       const int* __restrict__ p2, const int* __restrict__ r12,
                       const int* __restrict__ r22) {
    int id = blockIdx.x * blockDim.x + threadIdx.x;
    if (id >= NROLES) return;
    int term, s, loss;
    decode_role(id, p1, r11, p2, r12, r22, term, s, loss);
    int c = term / CHUNK;
    int pos = atomicAdd(&g_cur[s * NC + c], 1);
    g_list[pos] = (unsigned short)((term - c * CHUNK) | (loss << 15));
}

__global__ void k_pad() {    // pad sublist tails with dummy index CHUNK (terms[CHUNK]==0)
    int i = blockIdx.x * blockDim.x + threadIdx.x;
    if (i >= NCTR) return;
    int end = g_off[i + 1];
    for (int p = g_cur[i]; p < end; p++) g_list[p] = (unsigned short)CHUNK;
}

// ---------- main kernel: 4 rows/CTA, 2 CTAs/SM, gather-only ----------
__global__ __launch_bounds__(NT, 2) void three_phase_rhs(
    const float* __restrict__ t_in, const float* __restrict__ y_in,
    const float* __restrict__ den_gas,
    const float* __restrict__ a1, const float* __restrict__ g1,
    const float* __restrict__ a2, const float* __restrict__ g2,
    const int* __restrict__ r11, const int* __restrict__ r12,
    const int* __restrict__ r22,
    const int* __restrict__ inds_s, const int* __restrict__ inds_m,
    float* __restrict__ out)
{
    extern __shared__ float4 smem4[];
    float4* terms = smem4;                 // [CHUNK+1]; last is zero dummy
    float4* y4    = terms + (CHUNK + 1);   // [SB]
    __shared__ float red[16][NT / 32];
    __shared__ float tot[16];

    const int tid = threadIdx.x;
    const int b0 = blockIdx.x * ROWS;

    {
        const float* yr = y_in + (size_t)b0 * SB;
        for (int i = tid; i < SB; i += NT)
            y4[i] = make_float4(yr[i], yr[i + SB], yr[i + 2 * SB], yr[i + 3 * SB]);
    }
    if (tid == 0) terms[CHUNK] = make_float4(0.f, 0.f, 0.f, 0.f);

    float nI[ROWS], c2[ROWS];
    #pragma unroll
    for (int r = 0; r < ROWS; r++) {
        float T = 10.0f + 5.0f / (1.0f + __expf(-__ldg(t_in + b0 + r)));
        nI[r] = -1.0f / T;
        c2[r] = sqrtf(T * (1.0f / 300.0f)) * __ldg(den_gas + b0 + r);
    }
    const int s0 = __ldg(&inds_s[0]), m0 = __ldg(&inds_m[0]);

    bool isSurf[SPT], isMant[SPT];
    #pragma unroll
    for (int gsp = 0; gsp < SPT; gsp++) {
        int s = tid + gsp * NT;
        isSurf[gsp] = (unsigned)(s - s0) < NSS;
        isMant[gsp] = (unsigned)(s - m0) < NSS;
    }
    __syncthreads();

    float net[SPT][ROWS];
    float ng[ROWS];                     // only one gsp can be surface
    #pragma unroll
    for (int g = 0; g < SPT; g++)
        #pragma unroll
        for (int r = 0; r < ROWS; r++) net[g][r] = 0.f;
    #pragma unroll
    for (int r = 0; r < ROWS; r++) ng[r] = 0.f;

    for (int c = 0; c < NC; c++) {
        const int base = c * CHUNK;
        const int clen = min(CHUNK, NTERMS - base);

        // ---- phase 1: terms for this chunk ----
        for (int jj = tid; jj < clen; jj += NT) {
            int j = base + jj;
            float4 tv;
            if (j < N1) {
                float a = __ldg(a1 + j), g = __ldg(g1 + j);
                int   rr = __ldg(r11 + j);
                float4 yv = y4[rr];
                tv.x = a * __expf(g * nI[0]) * yv.x;
                tv.y = a * __expf(g * nI[1]) * yv.y;
                tv.z = a * __expf(g * nI[2]) * yv.z;
                tv.w = a * __expf(g * nI[3]) * yv.w;
            } else {
                int j2 = j - N1;
                float a = __ldg(a2 + j2), g = __ldg(g2 + j2);
                int  rA = __ldg(r12 + j2), rB = __ldg(r22 + j2);
                float4 ya = y4[rA], yb = y4[rB];
                tv.x = a * c2[0] * __expf(g * nI[0]) * ya.x * yb.x;
                tv.y = a * c2[1] * __expf(g * nI[1]) * ya.y * yb.y;
                tv.z = a * c2[2] * __expf(g * nI[2]) * ya.z * yb.z;
                tv.w = a * c2[3] * __expf(g * nI[3]) * ya.w * yb.w;
            }
            terms[jj] = tv;
        }
        __syncthreads();

        // ---- phase 2: gather this chunk's sublists (sign in bit 15) ----
        #pragma unroll
        for (int gsp = 0; gsp < SPT; gsp++) {
            const int s = tid + gsp * NT;
            const int ob = s * NC + c;
            const int beg = __ldg(&g_off[ob]);
            const int end = __ldg(&g_off[ob + 1]);
            const bool surf = isSurf[gsp];
            for (int i = beg; i < end; i += 2) {
                const unsigned w = *(const unsigned*)(g_list + i);
                #pragma unroll
                for (int h = 0; h < 2; h++) {
                    const unsigned e = (h == 0) ? (w & 0xFFFFu) : (w >> 16);
                    const int idx = (int)(e & 0x7FFFu);
                    const unsigned sx = (e & 0x8000u) << 16;    // fp sign flip
                    float4 tv = terms[idx];
                    net[gsp][0] += __int_as_float(__float_as_int(tv.x) ^ sx);
                    net[gsp][1] += __int_as_float(__float_as_int(tv.y) ^ sx);
                    net[gsp][2] += __int_as_float(__float_as_int(tv.z) ^ sx);
                    net[gsp][3] += __int_as_float(__float_as_int(tv.w) ^ sx);
                    if (surf && (e & 0x8000u)) {
                        ng[0] += tv.x; ng[1] += tv.y; ng[2] += tv.z; ng[3] += tv.w;
                    }
                }
            }
        }
        __syncthreads();
    }

    // ---- reductions: per row {gain, loss, ysurf, ymant} ----
    float vals[16];
    #pragma unroll
    for (int v = 0; v < 16; v++) vals[v] = 0.f;
    #pragma unroll
    for (int gsp = 0; gsp < SPT; gsp++) {
        int s = tid + gsp * NT;
        float4 yv = y4[s];
        float yr[ROWS] = { yv.x, yv.y, yv.z, yv.w };
        if (isSurf[gsp]) {
            #pragma unroll
            for (int r = 0; r < ROWS; r++) {
                vals[4 * r + 0] += net[gsp][r] + ng[r];   // gain
                vals[4 * r + 1] += ng[r];                 // loss
                vals[4 * r + 2] += yr[r];                 // y_surf_tot
            }
        } else if (isMant[gsp]) {
            #pragma unroll
            for (int r = 0; r < ROWS; r++) vals[4 * r + 3] += yr[r];
        }
    }
    {
        int lane = tid & 31, w = tid >> 5;
        #pragma unroll
        for (int v = 0; v < 16; v++) {
            float x = warp_red(vals[v]);
            if (lane == 0) red[v][w] = x;
        }
        __syncthreads();
        if (tid < 16) {
            float s = 0.f;
            #pragma unroll
            for (int i = 0; i < NT / 32; i++) s += red[tid][i];
            tot[tid] = s;
        }
        __syncthreads();
    }

    float ks2m[ROWS], km2s[ROWS];
    #pragma unroll
    for (int r = 0; r < ROWS; r++) {
        ks2m[r] = tot[4 * r + 0] / (tot[4 * r + 2] + 1e-10f);
        km2s[r] = tot[4 * r + 1] / (tot[4 * r + 3] + 1e-10f);
    }

    // ---- epilogue: surface<->mantle transfer + write out ----
    #pragma unroll
    for (int gsp = 0; gsp < SPT; gsp++) {
        int s = tid + gsp * NT;
        float dy[ROWS];
        #pragma unroll
        for (int r = 0; r < ROWS; r++) dy[r] = net[gsp][r];
        unsigned ds = (unsigned)(s - s0), dm = (unsigned)(s - m0);
        if (ds < NSS) {
            float4 ym = y4[m0 + ds], ys = y4[s];
            float ymr[ROWS] = { ym.x, ym.y, ym.z, ym.w };
            float ysr[ROWS] = { ys.x, ys.y, ys.z, ys.w };
            #pragma unroll
            for (int r = 0; r < ROWS; r++) dy[r] += km2s[r] * ymr[r] - ks2m[r] * ysr[r];
        } else if (dm < NSS) {
            float4 ys = y4[s0 + dm], ym = y4[s];
            float ysr[ROWS] = { ys.x, ys.y, ys.z, ys.w };
            float ymr[ROWS] = { ym.x, ym.y, ym.z, ym.w };
            #pragma unroll
            for (int r = 0; r < ROWS; r++) dy[r] += ks2m[r] * ysr[r] - km2s[r] * ymr[r];
        }
        #pragma unroll
        for (int r = 0; r < ROWS; r++)
            out[(size_t)(b0 + r) * SB + s] = dy[r];
    }
}

extern "C" void kernel_launch(void* const* d_in, const int* in_sizes, int n_in,
                              void* d_out, int out_size) {
    const float* t_in    = (const float*)d_in[0];
    const float* y_in    = (const float*)d_in[1];
    const float* den_gas = (const float*)d_in[2];
    const float* a1      = (const float*)d_in[3];
    const float* g1      = (const float*)d_in[4];
    const float* a2      = (const float*)d_in[5];
    const float* g2      = (const float*)d_in[6];
    const int*   r11     = (const int*)d_in[7];
    const int*   p1      = (const int*)d_in[8];
    const int*   r12     = (const int*)d_in[9];
    const int*   r22     = (const int*)d_in[10];
    const int*   p2      = (const int*)d_in[11];
    const int*   inds_s  = (const int*)d_in[12];
    const int*   inds_m  = (const int*)d_in[13];
    float*       out     = (float*)d_out;

    const int B = in_sizes[0];

    cudaFuncSetAttribute(three_phase_rhs,
                         cudaFuncAttributeMaxDynamicSharedMemorySize, SMEM_BYTES);

    k_zero <<<(NCTR   + 255) / 256, 256>>>();
    k_count<<<(NROLES + 255) / 256, 256>>>(p1, r11, p2, r12, r22);
    k_scan <<<1, 1024>>>();
    k_fill <<<(NROLES + 255) / 256, 256>>>(p1, r11, p2, r12, r22);
    k_pad  <<<(NCTR   + 255) / 256, 256>>>();

    three_phase_rhs<<<B / ROWS, NT, SMEM_BYTES>>>(
        t_in, y_in, den_gas, a1, g1, a2, g2,
        r11, r12, r22, inds_s, inds_m, out);
}